// round 1
// baseline (speedup 1.0000x reference)
#include <cuda_runtime.h>
#include <cuda_bf16.h>

// SimOTA dynamic label assignment.
// Inputs (metadata order):
//   0: pred_scores   (A*80) f32
//   1: pred_bboxes   (A*4)  f32
//   2: anchor_points (A*2)  f32
//   3: gt_labels     (G)    i32
//   4: gt_bboxes     (G*4)  f32
// Output (f32, concatenated): labels (A) | bboxes (A*4) | scores (A*81)

#define A_MAX 33600
#define G_MAX 256
#define TOPK 10
#define NCLS 80

__device__ float g_total_neg[A_MAX];
__device__ float g_area_p[A_MAX];
__device__ int   g_assigned[A_MAX];
__device__ int   g_topk[G_MAX * TOPK];
__device__ int   g_dynk[G_MAX];
__device__ int   g_lab[A_MAX];
__device__ float g_sval[A_MAX];

// ---------------------------------------------------------------------------
// Kernel A: per-anchor total_neg = sum_c softplus(s_c), area_p, init assigned.
// softplus(x) = max(x,0) + log1p(exp(-|x|))  (matches jax.nn.softplus = logaddexp(x,0))
// ---------------------------------------------------------------------------
__global__ void precompute_kernel(const float* __restrict__ scores,
                                  const float* __restrict__ pbox, int A) {
    int a = blockIdx.x * blockDim.x + threadIdx.x;
    if (a >= A) return;
    const float* row = scores + (size_t)a * NCLS;
    float tn = 0.f;
    #pragma unroll 8
    for (int c = 0; c < NCLS; c++) {
        float s = row[c];
        float L = log1pf(expf(-fabsf(s)));
        float spn = __fadd_rn(fmaxf(s, 0.f), L);
        tn = __fadd_rn(tn, spn);   // sequential sum, matching row reduction
    }
    g_total_neg[a] = tn;
    float4 pb = reinterpret_cast<const float4*>(pbox)[a];
    g_area_p[a] = __fmul_rn(__fsub_rn(pb.z, pb.x), __fsub_rn(pb.w, pb.y));
    g_assigned[a] = -1;
}

// ---------------------------------------------------------------------------
// Kernel B: one block per GT. Scan all anchors, compute cost only for inside
// anchors (outside cost collapses to exactly 1e10f in fp32 since base < 512),
// keep top-10 (cost asc, index asc tie-break = jax top_k(-cost) semantics),
// and count dyn_k = clip(#(inside & iou>0), 1, 10).
// key = (float_bits(cost) << 32) | anchor_index  -> uint64 lexicographic min.
// ---------------------------------------------------------------------------
__global__ __launch_bounds__(256)
void cost_topk_kernel(const float* __restrict__ scores,
                      const float* __restrict__ pbox,
                      const float* __restrict__ apts,
                      const int*   __restrict__ glab,
                      const float* __restrict__ gbox, int A) {
    int g = blockIdx.x;
    int tid = threadIdx.x;

    float x1 = gbox[g * 4 + 0], y1 = gbox[g * 4 + 1];
    float x2 = gbox[g * 4 + 2], y2 = gbox[g * 4 + 3];
    int label = glab[g];
    float areag = __fmul_rn(__fsub_rn(x2, x1), __fsub_rn(y2, y1));

    unsigned long long loc[TOPK];
    #pragma unroll
    for (int k = 0; k < TOPK; k++) loc[k] = 0xFFFFFFFFFFFFFFFFULL;
    int cnt = 0;

    const unsigned long long OUTHI =
        ((unsigned long long)__float_as_uint(1e10f)) << 32;
    const float2* ap2 = reinterpret_cast<const float2*>(apts);

    for (int a = tid; a < A; a += 256) {
        float2 p = ap2[a];
        unsigned long long key;
        // inside == in_gt (center region with radius 2.5*wh strictly contains the box)
        if (p.x >= x1 && p.x <= x2 && p.y >= y1 && p.y <= y2) {
            float4 pb = reinterpret_cast<const float4*>(pbox)[a];
            float ltx = fmaxf(pb.x, x1), lty = fmaxf(pb.y, y1);
            float rbx = fminf(pb.z, x2), rby = fminf(pb.w, y2);
            float w = fmaxf(__fsub_rn(rbx, ltx), 0.f);
            float h = fmaxf(__fsub_rn(rby, lty), 0.f);
            float ov = __fmul_rn(w, h);
            cnt += (ov > 0.f);
            float denom = __fadd_rn(__fsub_rn(__fadd_rn(g_area_p[a], areag), ov), 1e-6f);
            float iou = __fdiv_rn(ov, denom);
            float ic = -logf(fmaxf(iou, 1e-7f));
            float s = scores[(size_t)a * NCLS + label];
            float L = log1pf(expf(-fabsf(s)));
            float spp = __fadd_rn(fmaxf(-s, 0.f), L);
            float spn = __fadd_rn(fmaxf(s, 0.f), L);
            float cls = __fadd_rn(g_total_neg[a], __fsub_rn(spp, spn));
            float cost = __fadd_rn(cls, __fmul_rn(3.0f, ic));
            key = (((unsigned long long)__float_as_uint(cost)) << 32) | (unsigned)a;
        } else {
            key = OUTHI | (unsigned)a;
        }
        if (key < loc[TOPK - 1]) {
            loc[TOPK - 1] = key;
            #pragma unroll
            for (int k = TOPK - 1; k > 0; k--) {
                unsigned long long lo = loc[k - 1], hi = loc[k];
                if (hi < lo) { loc[k] = lo; loc[k - 1] = hi; }
            }
        }
    }

    __shared__ unsigned long long sh[256 * TOPK];
    __shared__ unsigned long long red[256];
    __shared__ int scnt;
    if (tid == 0) scnt = 0;
    #pragma unroll
    for (int k = 0; k < TOPK; k++) sh[tid * TOPK + k] = loc[k];
    __syncthreads();
    atomicAdd(&scnt, cnt);
    __syncthreads();
    if (tid == 0) {
        int c = scnt;
        g_dynk[g] = c < 1 ? 1 : (c > TOPK ? TOPK : c);
    }

    int ptr = 0;
    for (int r = 0; r < TOPK; r++) {
        red[tid] = (ptr < TOPK) ? sh[tid * TOPK + ptr] : 0xFFFFFFFFFFFFFFFFULL;
        __syncthreads();
        #pragma unroll
        for (int s = 128; s > 0; s >>= 1) {
            if (tid < s) {
                unsigned long long o = red[tid + s];
                if (o < red[tid]) red[tid] = o;
            }
            __syncthreads();
        }
        unsigned long long win = red[0];
        if (ptr < TOPK && sh[tid * TOPK + ptr] == win) ptr++;
        if (tid == 0) g_topk[g * TOPK + r] = (int)(win & 0xFFFFFFFFu);
        __syncthreads();
    }
}

// ---------------------------------------------------------------------------
// Kernel C: scatter-max assigned_gt[anchor] = max(g) over (g, rank<dyn_k[g]).
// ---------------------------------------------------------------------------
__global__ void scatter_kernel(int G) {
    int i = blockIdx.x * blockDim.x + threadIdx.x;
    if (i >= G * TOPK) return;
    int g = i / TOPK, r = i - g * TOPK;
    if (r < g_dynk[g]) atomicMax(&g_assigned[g_topk[i]], g);
}

// ---------------------------------------------------------------------------
// Kernel D: per-anchor labels + bboxes; stash (label, score value) for E.
// ---------------------------------------------------------------------------
__global__ void finalize1_kernel(const float* __restrict__ pbox,
                                 const int*   __restrict__ glab,
                                 const float* __restrict__ gbox,
                                 float* __restrict__ out, int A) {
    int a = blockIdx.x * blockDim.x + threadIdx.x;
    if (a >= A) return;
    int g = g_assigned[a];
    bool pos = g >= 0;
    int gs = pos ? g : 0;
    float bx1 = gbox[gs * 4 + 0], by1 = gbox[gs * 4 + 1];
    float bx2 = gbox[gs * 4 + 2], by2 = gbox[gs * 4 + 3];
    float4 pb = reinterpret_cast<const float4*>(pbox)[a];
    float ltx = fmaxf(pb.x, bx1), lty = fmaxf(pb.y, by1);
    float rbx = fminf(pb.z, bx2), rby = fminf(pb.w, by2);
    float w = fmaxf(__fsub_rn(rbx, ltx), 0.f);
    float h = fmaxf(__fsub_rn(rby, lty), 0.f);
    float ov = __fmul_rn(w, h);
    float areag = __fmul_rn(__fsub_rn(bx2, bx1), __fsub_rn(by2, by1));
    float denom = __fadd_rn(__fsub_rn(__fadd_rn(g_area_p[a], areag), ov), 1e-6f);
    float iou = __fdiv_rn(ov, denom);

    int lab = pos ? glab[gs] : NCLS;
    out[a] = (float)lab;
    float* ob = out + A + (size_t)a * 4;
    ob[0] = pos ? bx1 : 0.f;
    ob[1] = pos ? by1 : 0.f;
    ob[2] = pos ? bx2 : 0.f;
    ob[3] = pos ? by2 : 0.f;
    g_lab[a] = lab;
    g_sval[a] = pos ? iou : 0.f;
}

// ---------------------------------------------------------------------------
// Kernel E: scores (A x 81) one-hot fill.
// ---------------------------------------------------------------------------
__global__ void finalize2_kernel(float* __restrict__ out, int A) {
    int idx = blockIdx.x * blockDim.x + threadIdx.x;
    int total = A * (NCLS + 1);
    if (idx >= total) return;
    int a = idx / (NCLS + 1);
    int c = idx - a * (NCLS + 1);
    float v = (c == g_lab[a]) ? g_sval[a] : 0.f;
    out[(size_t)5 * A + idx] = v;
}

extern "C" void kernel_launch(void* const* d_in, const int* in_sizes, int n_in,
                              void* d_out, int out_size) {
    const float* scores = (const float*)d_in[0];
    const float* pbox   = (const float*)d_in[1];
    const float* apts   = (const float*)d_in[2];
    const int*   glab   = (const int*)d_in[3];
    const float* gbox   = (const float*)d_in[4];
    float* out = (float*)d_out;

    int A = in_sizes[2] / 2;   // anchor_points (A,2)
    int G = in_sizes[3];       // gt_labels (G,)

    precompute_kernel<<<(A + 255) / 256, 256>>>(scores, pbox, A);
    cost_topk_kernel<<<G, 256>>>(scores, pbox, apts, glab, gbox, A);
    scatter_kernel<<<(G * TOPK + 255) / 256, 256>>>(G);
    finalize1_kernel<<<(A + 255) / 256, 256>>>(pbox, glab, gbox, out, A);
    int total = A * (NCLS + 1);
    finalize2_kernel<<<(total + 255) / 256, 256>>>(out, A);
}

// round 2
// speedup vs baseline: 1.2030x; 1.2030x over previous
#include <cuda_runtime.h>
#include <cuda_bf16.h>

// SimOTA dynamic label assignment — spatially binned version.
// Inputs: 0 pred_scores (A*80) f32 | 1 pred_bboxes (A*4) f32 |
//         2 anchor_points (A*2) f32 | 3 gt_labels (G) i32 | 4 gt_bboxes (G*4) f32
// Output f32: labels (A) | bboxes (A*4) | scores (A*81)

#define A_MAX 33600
#define G_MAX 256
#define TOPK 10
#define NCLS 80
#define GRIDW 20
#define NCELLS (GRIDW * GRIDW)
#define INV_CELL (1.0f / 64.0f)

__device__ float g_total_neg[A_MAX];
__device__ float g_area_p[A_MAX];
__device__ int   g_assigned[A_MAX];
__device__ int   g_cnt[NCELLS];
__device__ int   g_off[NCELLS + 1];
__device__ int   g_cur[NCELLS];
__device__ int   g_sa_idx[A_MAX];
__device__ float2 g_sa_pt[A_MAX];
__device__ int   g_topk[G_MAX * TOPK];
__device__ int   g_dynk[G_MAX];

// ---------------------------------------------------------------------------
// K0: zero bin counters + zero-fill the scores region (A x 81) with float4.
// ---------------------------------------------------------------------------
__global__ void init_kernel(float* __restrict__ out, int A) {
    int i = blockIdx.x * blockDim.x + threadIdx.x;
    if (i < NCELLS) g_cnt[i] = 0;
    int n4 = (A * (NCLS + 1)) >> 2;          // A*81 divisible by 4 for A=33600
    float4* dst = reinterpret_cast<float4*>(out + (size_t)5 * A);
    if (i < n4) dst[i] = make_float4(0.f, 0.f, 0.f, 0.f);
}

// ---------------------------------------------------------------------------
// K1: per-anchor total_neg (sequential c-order, bit-identical to round 1),
// area_p, assigned=-1, and bin count. float4 loads for the score row.
// ---------------------------------------------------------------------------
__global__ void precompute_kernel(const float* __restrict__ scores,
                                  const float* __restrict__ pbox,
                                  const float* __restrict__ apts, int A) {
    int a = blockIdx.x * blockDim.x + threadIdx.x;
    if (a >= A) return;
    const float4* row = reinterpret_cast<const float4*>(scores + (size_t)a * NCLS);
    float tn = 0.f;
    #pragma unroll 5
    for (int q = 0; q < NCLS / 4; q++) {
        float4 v = row[q];
        float s;
        s = v.x; tn = __fadd_rn(tn, __fadd_rn(fmaxf(s, 0.f), log1pf(expf(-fabsf(s)))));
        s = v.y; tn = __fadd_rn(tn, __fadd_rn(fmaxf(s, 0.f), log1pf(expf(-fabsf(s)))));
        s = v.z; tn = __fadd_rn(tn, __fadd_rn(fmaxf(s, 0.f), log1pf(expf(-fabsf(s)))));
        s = v.w; tn = __fadd_rn(tn, __fadd_rn(fmaxf(s, 0.f), log1pf(expf(-fabsf(s)))));
    }
    g_total_neg[a] = tn;
    float4 pb = reinterpret_cast<const float4*>(pbox)[a];
    g_area_p[a] = __fmul_rn(__fsub_rn(pb.z, pb.x), __fsub_rn(pb.w, pb.y));
    g_assigned[a] = -1;
    float2 p = reinterpret_cast<const float2*>(apts)[a];
    int cx = min(GRIDW - 1, (int)(p.x * INV_CELL));
    int cy = min(GRIDW - 1, (int)(p.y * INV_CELL));
    atomicAdd(&g_cnt[cy * GRIDW + cx], 1);
}

// ---------------------------------------------------------------------------
// K2: single-block prefix sum over 400 cell counts -> offsets + cursors.
// ---------------------------------------------------------------------------
__global__ void scan_kernel() {
    __shared__ int sh[512];
    int t = threadIdx.x;
    int c = (t < NCELLS) ? g_cnt[t] : 0;
    sh[t] = c;
    __syncthreads();
    for (int o = 1; o < 512; o <<= 1) {
        int add = (t >= o) ? sh[t - o] : 0;
        __syncthreads();
        sh[t] += add;
        __syncthreads();
    }
    if (t < NCELLS) {
        g_off[t + 1] = sh[t];
        g_cur[t] = sh[t] - c;   // exclusive prefix
    }
    if (t == 0) g_off[0] = 0;
}

// ---------------------------------------------------------------------------
// K3: scatter anchors into cell-sorted order (index + point coords).
// ---------------------------------------------------------------------------
__global__ void binsort_kernel(const float* __restrict__ apts, int A) {
    int a = blockIdx.x * blockDim.x + threadIdx.x;
    if (a >= A) return;
    float2 p = reinterpret_cast<const float2*>(apts)[a];
    int cx = min(GRIDW - 1, (int)(p.x * INV_CELL));
    int cy = min(GRIDW - 1, (int)(p.y * INV_CELL));
    int pos = atomicAdd(&g_cur[cy * GRIDW + cx], 1);
    g_sa_idx[pos] = a;
    g_sa_pt[pos] = p;
}

// ---------------------------------------------------------------------------
// K4: one WARP per GT. Scan only cells overlapping the GT box; maintain
// per-lane register top-10 of (cost_bits<<32)|idx; shfl merge; count
// cnt = #(inside & iou>0) and icnt = #inside. Fallback: icnt==0 -> anchor 0.
// ---------------------------------------------------------------------------
__global__ __launch_bounds__(256)
void cost_topk_kernel(const float* __restrict__ scores,
                      const float* __restrict__ pbox,
                      const int*   __restrict__ glab,
                      const float* __restrict__ gbox, int A, int G) {
    int gw = (blockIdx.x * blockDim.x + threadIdx.x) >> 5;
    int lane = threadIdx.x & 31;
    if (gw >= G) return;
    int g = gw;

    float x1 = gbox[g * 4 + 0], y1 = gbox[g * 4 + 1];
    float x2 = gbox[g * 4 + 2], y2 = gbox[g * 4 + 3];
    int label = glab[g];
    float areag = __fmul_rn(__fsub_rn(x2, x1), __fsub_rn(y2, y1));

    int cx0 = max(0, min(GRIDW - 1, (int)(x1 * INV_CELL)));
    int cx1 = max(0, min(GRIDW - 1, (int)(x2 * INV_CELL)));
    int cy0 = max(0, min(GRIDW - 1, (int)(y1 * INV_CELL)));
    int cy1 = max(0, min(GRIDW - 1, (int)(y2 * INV_CELL)));

    unsigned long long loc[TOPK];
    #pragma unroll
    for (int k = 0; k < TOPK; k++) loc[k] = 0xFFFFFFFFFFFFFFFFULL;
    int cnt = 0, icnt = 0;

    for (int cy = cy0; cy <= cy1; cy++) {
        for (int cx = cx0; cx <= cx1; cx++) {
            int c = cy * GRIDW + cx;
            int s0 = g_off[c], e0 = g_off[c + 1];
            for (int i = s0 + lane; i < e0; i += 32) {
                float2 p = g_sa_pt[i];
                if (p.x >= x1 && p.x <= x2 && p.y >= y1 && p.y <= y2) {
                    icnt++;
                    int a = g_sa_idx[i];
                    float4 pb = reinterpret_cast<const float4*>(pbox)[a];
                    float ltx = fmaxf(pb.x, x1), lty = fmaxf(pb.y, y1);
                    float rbx = fminf(pb.z, x2), rby = fminf(pb.w, y2);
                    float w = fmaxf(__fsub_rn(rbx, ltx), 0.f);
                    float h = fmaxf(__fsub_rn(rby, lty), 0.f);
                    float ov = __fmul_rn(w, h);
                    cnt += (ov > 0.f);
                    float denom = __fadd_rn(__fsub_rn(__fadd_rn(g_area_p[a], areag), ov), 1e-6f);
                    float iou = __fdiv_rn(ov, denom);
                    float ic = -logf(fmaxf(iou, 1e-7f));
                    float s = scores[(size_t)a * NCLS + label];
                    float L = log1pf(expf(-fabsf(s)));
                    float spp = __fadd_rn(fmaxf(-s, 0.f), L);
                    float spn = __fadd_rn(fmaxf(s, 0.f), L);
                    float cls = __fadd_rn(g_total_neg[a], __fsub_rn(spp, spn));
                    float cost = __fadd_rn(cls, __fmul_rn(3.0f, ic));
                    unsigned long long key =
                        (((unsigned long long)__float_as_uint(cost)) << 32) | (unsigned)a;
                    if (key < loc[TOPK - 1]) {
                        loc[TOPK - 1] = key;
                        #pragma unroll
                        for (int k = TOPK - 1; k > 0; k--) {
                            unsigned long long lo = loc[k - 1], hi = loc[k];
                            if (hi < lo) { loc[k] = lo; loc[k - 1] = hi; }
                        }
                    }
                }
            }
        }
    }

    // warp-reduce counts
    #pragma unroll
    for (int o = 16; o; o >>= 1) {
        cnt  += __shfl_xor_sync(0xffffffffu, cnt, o);
        icnt += __shfl_xor_sync(0xffffffffu, icnt, o);
    }

    // warp-merge top-10 (keys unique => exactly one lane matches each winner)
    int ptr = 0;
    for (int r = 0; r < TOPK; r++) {
        unsigned long long v = 0xFFFFFFFFFFFFFFFFULL;
        #pragma unroll
        for (int k = 0; k < TOPK; k++) if (ptr == k) v = loc[k];
        unsigned long long m = v;
        #pragma unroll
        for (int o = 16; o; o >>= 1) {
            unsigned long long other = __shfl_xor_sync(0xffffffffu, m, o);
            if (other < m) m = other;
        }
        if (v == m) ptr++;
        if (lane == 0) g_topk[g * TOPK + r] = (int)(m & 0xFFFFFFFFULL);
    }

    if (lane == 0) {
        if (icnt == 0) g_topk[g * TOPK] = 0;   // all-outside GT: rank0 = anchor 0
        g_dynk[g] = min(max(cnt, 1), TOPK);
    }
}

// ---------------------------------------------------------------------------
// K5: scatter-max assigned_gt[anchor] = max(g) over (g, rank<dyn_k[g]).
// ---------------------------------------------------------------------------
__global__ void scatter_kernel(int G) {
    int i = blockIdx.x * blockDim.x + threadIdx.x;
    if (i >= G * TOPK) return;
    int g = i / TOPK, r = i - g * TOPK;
    if (r < g_dynk[g]) atomicMax(&g_assigned[g_topk[i]], g);
}

// ---------------------------------------------------------------------------
// K6: per-anchor labels + bboxes (float4) + single scattered score value.
// ---------------------------------------------------------------------------
__global__ void finalize_kernel(const float* __restrict__ pbox,
                                const int*   __restrict__ glab,
                                const float* __restrict__ gbox,
                                float* __restrict__ out, int A) {
    int a = blockIdx.x * blockDim.x + threadIdx.x;
    if (a >= A) return;
    int g = g_assigned[a];
    bool pos = g >= 0;
    int gs = pos ? g : 0;
    float4 gb = reinterpret_cast<const float4*>(gbox)[gs];
    float4 pb = reinterpret_cast<const float4*>(pbox)[a];
    float ltx = fmaxf(pb.x, gb.x), lty = fmaxf(pb.y, gb.y);
    float rbx = fminf(pb.z, gb.z), rby = fminf(pb.w, gb.w);
    float w = fmaxf(__fsub_rn(rbx, ltx), 0.f);
    float h = fmaxf(__fsub_rn(rby, lty), 0.f);
    float ov = __fmul_rn(w, h);
    float areag = __fmul_rn(__fsub_rn(gb.z, gb.x), __fsub_rn(gb.w, gb.y));
    float denom = __fadd_rn(__fsub_rn(__fadd_rn(g_area_p[a], areag), ov), 1e-6f);
    float iou = __fdiv_rn(ov, denom);

    int lab = pos ? glab[gs] : NCLS;
    out[a] = (float)lab;
    float4 ob = pos ? gb : make_float4(0.f, 0.f, 0.f, 0.f);
    reinterpret_cast<float4*>(out + A)[a] = ob;
    float v = pos ? iou : 0.f;
    out[(size_t)5 * A + (size_t)a * (NCLS + 1) + lab] = v;
}

extern "C" void kernel_launch(void* const* d_in, const int* in_sizes, int n_in,
                              void* d_out, int out_size) {
    const float* scores = (const float*)d_in[0];
    const float* pbox   = (const float*)d_in[1];
    const float* apts   = (const float*)d_in[2];
    const int*   glab   = (const int*)d_in[3];
    const float* gbox   = (const float*)d_in[4];
    float* out = (float*)d_out;

    int A = in_sizes[2] / 2;
    int G = in_sizes[3];

    int fill4 = (A * (NCLS + 1)) >> 2;
    init_kernel<<<(fill4 + 255) / 256, 256>>>(out, A);
    precompute_kernel<<<(A + 255) / 256, 256>>>(scores, pbox, apts, A);
    scan_kernel<<<1, 512>>>();
    binsort_kernel<<<(A + 255) / 256, 256>>>(apts, A);
    cost_topk_kernel<<<(G * 32 + 255) / 256, 256>>>(scores, pbox, glab, gbox, A, G);
    scatter_kernel<<<(G * TOPK + 255) / 256, 256>>>(G);
    finalize_kernel<<<(A + 255) / 256, 256>>>(pbox, glab, gbox, out, A);
}

// round 3
// speedup vs baseline: 1.3565x; 1.1276x over previous
#include <cuda_runtime.h>
#include <cuda_bf16.h>

// SimOTA dynamic label assignment — 3-kernel fused version.
// Inputs: 0 pred_scores (A*80) f32 | 1 pred_bboxes (A*4) f32 |
//         2 anchor_points (A*2) f32 | 3 gt_labels (G) i32 | 4 gt_bboxes (G*4) f32
// Output f32: labels (A) | bboxes (A*4) | scores (A*81)

#define A_MAX 33600
#define G_MAX 256
#define TOPK 10
#define NCLS 80
#define GRIDW 20
#define NCELLS (GRIDW * GRIDW)
#define INV_CELL (1.0f / 64.0f)
#define CAP 224   // max anchors per 64px cell; uniform A=33600 -> mean 84, 20-sigma safe

__device__ float  g_total_neg[A_MAX];
__device__ float  g_area_p[A_MAX];
__device__ int    g_assigned[A_MAX];
__device__ int    g_cnt[NCELLS];          // zero at module load; K3 re-zeroes each call
__device__ int    g_sa_idx[NCELLS * CAP];
__device__ float2 g_sa_pt[NCELLS * CAP];

// ---------------------------------------------------------------------------
// K1: fused zero-fill of scores region + per-anchor precompute + bin insert.
// grid covers max(A, A*81/4) threads.
// ---------------------------------------------------------------------------
__global__ __launch_bounds__(256)
void fused_pre_kernel(const float* __restrict__ scores,
                      const float* __restrict__ pbox,
                      const float* __restrict__ apts,
                      float* __restrict__ out, int A) {
    int i = blockIdx.x * blockDim.x + threadIdx.x;

    int n4 = (A * (NCLS + 1)) >> 2;
    if (i < n4)
        reinterpret_cast<float4*>(out + (size_t)5 * A)[i] =
            make_float4(0.f, 0.f, 0.f, 0.f);
    if (i == 0) {   // tail (none for A=33600, kept for generality)
        for (int t = n4 * 4; t < A * (NCLS + 1); t++) out[(size_t)5 * A + t] = 0.f;
    }

    if (i >= A) return;
    int a = i;

    // total_neg: sequential class order (bit-exact vs reference selection path)
    const float4* row = reinterpret_cast<const float4*>(scores + (size_t)a * NCLS);
    float tn = 0.f;
    #pragma unroll 5
    for (int q = 0; q < NCLS / 4; q++) {
        float4 v = row[q];
        float s;
        s = v.x; tn = __fadd_rn(tn, __fadd_rn(fmaxf(s, 0.f), log1pf(expf(-fabsf(s)))));
        s = v.y; tn = __fadd_rn(tn, __fadd_rn(fmaxf(s, 0.f), log1pf(expf(-fabsf(s)))));
        s = v.z; tn = __fadd_rn(tn, __fadd_rn(fmaxf(s, 0.f), log1pf(expf(-fabsf(s)))));
        s = v.w; tn = __fadd_rn(tn, __fadd_rn(fmaxf(s, 0.f), log1pf(expf(-fabsf(s)))));
    }
    g_total_neg[a] = tn;

    float4 pb = reinterpret_cast<const float4*>(pbox)[a];
    g_area_p[a] = __fmul_rn(__fsub_rn(pb.z, pb.x), __fsub_rn(pb.w, pb.y));
    g_assigned[a] = -1;

    float2 p = reinterpret_cast<const float2*>(apts)[a];
    int cx = min(GRIDW - 1, max(0, (int)(p.x * INV_CELL)));
    int cy = min(GRIDW - 1, max(0, (int)(p.y * INV_CELL)));
    int cell = cy * GRIDW + cx;
    int slot = atomicAdd(&g_cnt[cell], 1);
    if (slot < CAP) {
        g_sa_idx[cell * CAP + slot] = a;
        g_sa_pt[cell * CAP + slot] = p;
    }
}

// ---------------------------------------------------------------------------
// K2: one warp (= one block of 32) per GT. Scan overlapping cells, register
// top-10 of (cost_bits<<32)|idx, shfl merge, then fused atomicMax scatter.
// ---------------------------------------------------------------------------
__global__ __launch_bounds__(32)
void cost_topk_scatter_kernel(const float* __restrict__ scores,
                              const float* __restrict__ pbox,
                              const int*   __restrict__ glab,
                              const float* __restrict__ gbox, int G) {
    int g = blockIdx.x;
    if (g >= G) return;
    int lane = threadIdx.x;

    float4 gb = reinterpret_cast<const float4*>(gbox)[g];
    float x1 = gb.x, y1 = gb.y, x2 = gb.z, y2 = gb.w;
    int label = glab[g];
    float areag = __fmul_rn(__fsub_rn(x2, x1), __fsub_rn(y2, y1));

    int cx0 = max(0, min(GRIDW - 1, (int)(x1 * INV_CELL)));
    int cx1 = max(0, min(GRIDW - 1, (int)(x2 * INV_CELL)));
    int cy0 = max(0, min(GRIDW - 1, (int)(y1 * INV_CELL)));
    int cy1 = max(0, min(GRIDW - 1, (int)(y2 * INV_CELL)));

    unsigned long long loc[TOPK];
    #pragma unroll
    for (int k = 0; k < TOPK; k++) loc[k] = 0xFFFFFFFFFFFFFFFFULL;
    int cnt = 0, icnt = 0;

    for (int cy = cy0; cy <= cy1; cy++) {
        for (int cx = cx0; cx <= cx1; cx++) {
            int c = cy * GRIDW + cx;
            int n = min(g_cnt[c], CAP);
            int base = c * CAP;
            for (int i = lane; i < n; i += 32) {
                float2 p = g_sa_pt[base + i];
                if (p.x >= x1 && p.x <= x2 && p.y >= y1 && p.y <= y2) {
                    icnt++;
                    int a = g_sa_idx[base + i];
                    float4 pb = reinterpret_cast<const float4*>(pbox)[a];
                    float ltx = fmaxf(pb.x, x1), lty = fmaxf(pb.y, y1);
                    float rbx = fminf(pb.z, x2), rby = fminf(pb.w, y2);
                    float w = fmaxf(__fsub_rn(rbx, ltx), 0.f);
                    float h = fmaxf(__fsub_rn(rby, lty), 0.f);
                    float ov = __fmul_rn(w, h);
                    cnt += (ov > 0.f);
                    float denom = __fadd_rn(__fsub_rn(__fadd_rn(g_area_p[a], areag), ov), 1e-6f);
                    float iou = __fdiv_rn(ov, denom);
                    float ic = -logf(fmaxf(iou, 1e-7f));
                    float s = scores[(size_t)a * NCLS + label];
                    float L = log1pf(expf(-fabsf(s)));
                    float spp = __fadd_rn(fmaxf(-s, 0.f), L);
                    float spn = __fadd_rn(fmaxf(s, 0.f), L);
                    float cls = __fadd_rn(g_total_neg[a], __fsub_rn(spp, spn));
                    float cost = __fadd_rn(cls, __fmul_rn(3.0f, ic));
                    unsigned long long key =
                        (((unsigned long long)__float_as_uint(cost)) << 32) | (unsigned)a;
                    if (key < loc[TOPK - 1]) {
                        loc[TOPK - 1] = key;
                        #pragma unroll
                        for (int k = TOPK - 1; k > 0; k--) {
                            unsigned long long lo = loc[k - 1], hi = loc[k];
                            if (hi < lo) { loc[k] = lo; loc[k - 1] = hi; }
                        }
                    }
                }
            }
        }
    }

    #pragma unroll
    for (int o = 16; o; o >>= 1) {
        cnt  += __shfl_xor_sync(0xffffffffu, cnt, o);
        icnt += __shfl_xor_sync(0xffffffffu, icnt, o);
    }
    int dynk = min(max(cnt, 1), TOPK);

    // warp-merge: lane r ends holding the rank-r winner's anchor index
    unsigned win = 0xFFFFFFFFu;
    int ptr = 0;
    for (int r = 0; r < TOPK; r++) {
        unsigned long long v = 0xFFFFFFFFFFFFFFFFULL;
        #pragma unroll
        for (int k = 0; k < TOPK; k++) if (ptr == k) v = loc[k];
        unsigned long long m = v;
        #pragma unroll
        for (int o = 16; o; o >>= 1) {
            unsigned long long other = __shfl_xor_sync(0xffffffffu, m, o);
            if (other < m) m = other;
        }
        if (v == m) ptr++;
        if (lane == r) win = (unsigned)(m & 0xFFFFFFFFULL);
    }

    // fused scatter: rank r < dynk -> atomicMax(assigned[win_r], g)
    if (icnt == 0) {
        // all anchors outside: reference top-k over uniform 1e10 picks indices
        // 0..9; only rank 0 (< dynk==1) is used -> anchor 0.
        if (lane == 0) atomicMax(&g_assigned[0], g);
    } else if (lane < dynk) {
        atomicMax(&g_assigned[win], g);
    }
}

// ---------------------------------------------------------------------------
// K3: finalize (2 anchors per thread for MLP) + reset bin counters for the
// next graph replay.
// ---------------------------------------------------------------------------
__global__ __launch_bounds__(128)
void finalize_kernel(const float* __restrict__ pbox,
                     const int*   __restrict__ glab,
                     const float* __restrict__ gbox,
                     float* __restrict__ out, int A) {
    int t = blockIdx.x * blockDim.x + threadIdx.x;
    if (t < NCELLS) g_cnt[t] = 0;

    int half = (A + 1) >> 1;
    #pragma unroll
    for (int rep = 0; rep < 2; rep++) {
        int a = t + rep * half;
        if (a >= A) break;
        int g = g_assigned[a];
        bool pos = g >= 0;
        int gs = pos ? g : 0;
        float4 gb = reinterpret_cast<const float4*>(gbox)[gs];
        float4 pb = reinterpret_cast<const float4*>(pbox)[a];
        float ltx = fmaxf(pb.x, gb.x), lty = fmaxf(pb.y, gb.y);
        float rbx = fminf(pb.z, gb.z), rby = fminf(pb.w, gb.w);
        float w = fmaxf(__fsub_rn(rbx, ltx), 0.f);
        float h = fmaxf(__fsub_rn(rby, lty), 0.f);
        float ov = __fmul_rn(w, h);
        float areag = __fmul_rn(__fsub_rn(gb.z, gb.x), __fsub_rn(gb.w, gb.y));
        float denom = __fadd_rn(__fsub_rn(__fadd_rn(g_area_p[a], areag), ov), 1e-6f);
        float iou = __fdiv_rn(ov, denom);

        int lab = pos ? glab[gs] : NCLS;
        out[a] = (float)lab;
        float4 ob = pos ? gb : make_float4(0.f, 0.f, 0.f, 0.f);
        reinterpret_cast<float4*>(out + A)[a] = ob;
        out[(size_t)5 * A + (size_t)a * (NCLS + 1) + lab] = pos ? iou : 0.f;
    }
}

extern "C" void kernel_launch(void* const* d_in, const int* in_sizes, int n_in,
                              void* d_out, int out_size) {
    const float* scores = (const float*)d_in[0];
    const float* pbox   = (const float*)d_in[1];
    const float* apts   = (const float*)d_in[2];
    const int*   glab   = (const int*)d_in[3];
    const float* gbox   = (const float*)d_in[4];
    float* out = (float*)d_out;

    int A = in_sizes[2] / 2;
    int G = in_sizes[3];

    int n4 = (A * (NCLS + 1)) >> 2;
    int k1_threads = n4 > A ? n4 : A;
    fused_pre_kernel<<<(k1_threads + 255) / 256, 256>>>(scores, pbox, apts, out, A);
    cost_topk_scatter_kernel<<<G, 32>>>(scores, pbox, glab, gbox, G);
    int half = (A + 1) >> 1;
    finalize_kernel<<<(half + 127) / 128, 128>>>(pbox, glab, gbox, out, A);
}